// round 8
// baseline (speedup 1.0000x reference)
#include <cuda_runtime.h>
#include <cstdint>

// Quantized SiLU (per-row scales), S=8192 rows, H=4096 cols.
//   x_f   = x * scale_x[row]
//   y_q   = clip(rint(sigmoid(x_f) / scale_y[row]), -127, 127)
//   y_f   = y_q * scale_y[row]
//   out_q = clip(rint((x_f * y_f) / scale_out[row]), -127, 127)
//
// x is int8-valued => only 255 distinct inputs per row. Each CTA (one row)
// builds a per-row LUT of out_q in shared memory, then the 4096 elements are
// index+LDS only.
//
// R8 change: LUT is replicated 32x and interleaved (lut[idx*32 + lane]) so
// each lane reads its own bank (bank = lane) -> ZERO bank conflicts, vs
// N~3.4 for the flat 255-entry layout. 32KB smem/CTA, build is 8 STS.128
// per thread, hidden under the front-batched global loads.
//
// x arrives promoted to a 4-byte type (int32 or float32); values always in
// [-127,127], so the index decodes per element branch-free.
// Output: float32 [S*H out_q values][S scale_out values].

#define LOG2E 1.44269504088896340736f

// word -> LUT index in [0,254]
__device__ __forceinline__ int decode_idx(int w) {
    float fi = (float)w;                              // int32 interpretation
    int   wf = __float2int_rn(__int_as_float(w));     // float32 interpretation
    return ((fabsf(fi) > 127.5f) ? wf : w) + 127;
}

__global__ void __launch_bounds__(256) silu_lut_kernel(
    const int4* __restrict__ x,
    const float* __restrict__ scale_x_v,
    const float* __restrict__ scale_y_v,
    const float* __restrict__ scale_out_v,
    float4* __restrict__ out,
    float* __restrict__ tail_dst,
    int write_tail)
{
    __shared__ float lut[256 * 32];    // 32 interleaved copies: [idx*32 + lane]
    int row = blockIdx.x;
    int t = threadIdx.x;
    int lane = t & 31;

    // front-batch the row's loads (MLP=4) so they fly during LUT build
    long base = (long)row * 1024 + t;
    int4 v0 = x[base];
    int4 v1 = x[base + 256];
    int4 v2 = x[base + 512];
    int4 v3 = x[base + 768];

    float scale_x = __ldg(&scale_x_v[row]);
    float scale_y = __ldg(&scale_y_v[row]);
    float scale_o = __ldg(&scale_out_v[row]);

    // build LUT: entry i corresponds to xb = i - 127 (full-precision math),
    // written to all 32 lane-slots (8 x st.shared.v4).
    if (t < 255) {
        float f   = (float)(t - 127);
        float xf  = f * scale_x;
        float e   = exp2f(-xf * LOG2E);               // exp(-x_f)
        float sig = __frcp_rn(1.0f + e);              // sigmoid(x_f)
        float yq  = fminf(rintf(sig / scale_y), 127.0f);  // sigmoid>0: upper clip only
        float oq  = rintf(xf * (yq * scale_y) / scale_o);
        oq = fminf(fmaxf(oq, -127.0f), 127.0f);
        float4 q = make_float4(oq, oq, oq, oq);
        float4* p = (float4*)&lut[t * 32];
        #pragma unroll
        for (int j = 0; j < 8; j++) p[j] = q;
    }
    if (write_tail && t == 0) tail_dst[row] = scale_o;
    __syncthreads();

    float4 r0, r1, r2, r3;
    r0.x = lut[decode_idx(v0.x) * 32 + lane];
    r0.y = lut[decode_idx(v0.y) * 32 + lane];
    r0.z = lut[decode_idx(v0.z) * 32 + lane];
    r0.w = lut[decode_idx(v0.w) * 32 + lane];
    r1.x = lut[decode_idx(v1.x) * 32 + lane];
    r1.y = lut[decode_idx(v1.y) * 32 + lane];
    r1.z = lut[decode_idx(v1.z) * 32 + lane];
    r1.w = lut[decode_idx(v1.w) * 32 + lane];
    r2.x = lut[decode_idx(v2.x) * 32 + lane];
    r2.y = lut[decode_idx(v2.y) * 32 + lane];
    r2.z = lut[decode_idx(v2.z) * 32 + lane];
    r2.w = lut[decode_idx(v2.w) * 32 + lane];
    r3.x = lut[decode_idx(v3.x) * 32 + lane];
    r3.y = lut[decode_idx(v3.y) * 32 + lane];
    r3.z = lut[decode_idx(v3.z) * 32 + lane];
    r3.w = lut[decode_idx(v3.w) * 32 + lane];

    out[base]       = r0;
    out[base + 256] = r1;
    out[base + 512] = r2;
    out[base + 768] = r3;
}

// Generic fallback for unexpected shapes (direct evaluation).
__device__ __forceinline__ float decode_elem(int w) {
    float fi = (float)w;
    float ff = __int_as_float(w);
    return (fabsf(fi) > 127.5f) ? ff : fi;
}

__global__ void __launch_bounds__(256) silu_quant_generic_kernel(
    const int* __restrict__ x,
    const float* __restrict__ scale_x_v,
    const float* __restrict__ scale_y_v,
    const float* __restrict__ scale_out_v,
    float* __restrict__ out,
    int H, long total)
{
    long i = (long)blockIdx.x * blockDim.x + threadIdx.x;
    if (i >= total) return;
    int row = (int)(i / H);
    float scale_x = scale_x_v[row];
    float scale_y = scale_y_v[row];
    float f   = decode_elem(x[i]);
    float xf  = f * scale_x;
    float e   = exp2f(-xf * LOG2E);
    float sig = __frcp_rn(1.0f + e);
    float yq  = fminf(rintf(sig / scale_y), 127.0f);
    float oq  = rintf(xf * (yq * scale_y) / scale_out_v[row]);
    out[i] = fminf(fmaxf(oq, -127.0f), 127.0f);
}

__global__ void tail_pad_kernel(const float* __restrict__ scale_o,
                                float* __restrict__ dst, int S, long extra) {
    long i = (long)blockIdx.x * blockDim.x + threadIdx.x;
    if (i >= extra) return;
    dst[i] = (i < S) ? scale_o[i] : 0.0f;
}

extern "C" void kernel_launch(void* const* d_in, const int* in_sizes, int n_in,
                              void* d_out, int out_size) {
    const void* x         = d_in[0];
    const float* scale_x  = (const float*)d_in[1];
    const float* scale_y  = (const float*)d_in[2];
    const float* scale_o  = (const float*)d_in[3];

    int S = in_sizes[1];            // rows (scale_x element count)
    int H = in_sizes[0] / S;        // cols
    long total = (long)S * H;
    long extra = (long)out_size - total;
    float* out = (float*)d_out;

    if (H == 4096) {
        int write_tail = (extra >= (long)S) ? 1 : 0;
        silu_lut_kernel<<<S, 256>>>(
            (const int4*)x, scale_x, scale_y, scale_o,
            (float4*)out, out + total, write_tail);
        if (extra > (long)S) {
            long pad = extra - S;
            tail_pad_kernel<<<(int)((pad + 255) / 256), 256>>>(
                scale_o + S, out + total + S, 0, pad);
        } else if (extra > 0 && !write_tail) {
            tail_pad_kernel<<<(int)((extra + 255) / 256), 256>>>(
                scale_o, out + total, (int)extra, extra);
        }
    } else {
        long blocks = (total + 255) / 256;
        silu_quant_generic_kernel<<<(unsigned)blocks, 256>>>(
            (const int*)x, scale_x, scale_y, scale_o, out, H, total);
        if (extra > 0) {
            tail_pad_kernel<<<(int)((extra + 255) / 256), 256>>>(
                scale_o, out + total, (int)(extra < S ? extra : S), extra);
        }
    }
}

// round 9
// speedup vs baseline: 1.7486x; 1.7486x over previous
#include <cuda_runtime.h>
#include <cstdint>

// Quantized SiLU (per-row scales), S=8192 rows, H=4096 cols.
//   x_f   = x * scale_x[row]
//   y_q   = clip(rint(sigmoid(x_f) / scale_y[row]), -127, 127)
//   y_f   = y_q * scale_y[row]
//   out_q = clip(rint((x_f * y_f) / scale_out[row]), -127, 127)
//
// x is int8-valued => only 255 distinct inputs per row. Each CTA (one row)
// builds a flat 255-entry LUT of out_q in shared memory (one exact eval per
// thread, conflict-free STS), then the 4096 row elements are index+LDS only.
// (R8 showed 32x-replicated LUTs lose: the build's 32-way STS conflicts cost
// more than the conflicted reads they remove; flat layout is near the smem
// traffic floor.)
//
// R9 delta vs the 43.5us R7 baseline: __ldcs/__stcs streaming hints on the
// 262MB read-once/write-once stream. Nothing else changed.
//
// x arrives promoted to a 4-byte type (int32 or float32); values always in
// [-127,127], so the index decodes per element branch-free.
// Output: float32 [S*H out_q values][S scale_out values].

#define LOG2E 1.44269504088896340736f

// word -> LUT index in [0,254]
__device__ __forceinline__ int decode_idx(int w) {
    float fi = (float)w;                              // int32 interpretation
    int   wf = __float2int_rn(__int_as_float(w));     // float32 interpretation
    return ((fabsf(fi) > 127.5f) ? wf : w) + 127;
}

__global__ void __launch_bounds__(256) silu_lut_kernel(
    const int4* __restrict__ x,
    const float* __restrict__ scale_x_v,
    const float* __restrict__ scale_y_v,
    const float* __restrict__ scale_out_v,
    float4* __restrict__ out,
    float* __restrict__ tail_dst,
    int write_tail)
{
    __shared__ float lut[255];
    int row = blockIdx.x;
    int t = threadIdx.x;

    // front-batch the row's loads (MLP=4, streaming) so they fly during LUT build
    long base = (long)row * 1024 + t;
    int4 v0 = __ldcs(x + base);
    int4 v1 = __ldcs(x + base + 256);
    int4 v2 = __ldcs(x + base + 512);
    int4 v3 = __ldcs(x + base + 768);

    float scale_x = __ldg(&scale_x_v[row]);
    float scale_y = __ldg(&scale_y_v[row]);
    float scale_o = __ldg(&scale_out_v[row]);

    // build LUT: entry i corresponds to xb = i - 127 (full-precision math);
    // thread t writes word t -> bank = lane -> conflict-free.
    if (t < 255) {
        float f   = (float)(t - 127);
        float xf  = f * scale_x;
        float e   = exp2f(-xf * LOG2E);               // exp(-x_f)
        float sig = __frcp_rn(1.0f + e);              // sigmoid(x_f)
        float yq  = fminf(rintf(sig / scale_y), 127.0f);  // sigmoid>0: upper clip only
        float oq  = rintf(xf * (yq * scale_y) / scale_o);
        lut[t] = fminf(fmaxf(oq, -127.0f), 127.0f);
    }
    if (write_tail && t == 0) tail_dst[row] = scale_o;
    __syncthreads();

    float4 r0, r1, r2, r3;
    r0.x = lut[decode_idx(v0.x)];
    r0.y = lut[decode_idx(v0.y)];
    r0.z = lut[decode_idx(v0.z)];
    r0.w = lut[decode_idx(v0.w)];
    r1.x = lut[decode_idx(v1.x)];
    r1.y = lut[decode_idx(v1.y)];
    r1.z = lut[decode_idx(v1.z)];
    r1.w = lut[decode_idx(v1.w)];
    r2.x = lut[decode_idx(v2.x)];
    r2.y = lut[decode_idx(v2.y)];
    r2.z = lut[decode_idx(v2.z)];
    r2.w = lut[decode_idx(v2.w)];
    r3.x = lut[decode_idx(v3.x)];
    r3.y = lut[decode_idx(v3.y)];
    r3.z = lut[decode_idx(v3.z)];
    r3.w = lut[decode_idx(v3.w)];

    __stcs(out + base,       r0);
    __stcs(out + base + 256, r1);
    __stcs(out + base + 512, r2);
    __stcs(out + base + 768, r3);
}

// Generic fallback for unexpected shapes (direct evaluation).
__device__ __forceinline__ float decode_elem(int w) {
    float fi = (float)w;
    float ff = __int_as_float(w);
    return (fabsf(fi) > 127.5f) ? ff : fi;
}

__global__ void __launch_bounds__(256) silu_quant_generic_kernel(
    const int* __restrict__ x,
    const float* __restrict__ scale_x_v,
    const float* __restrict__ scale_y_v,
    const float* __restrict__ scale_out_v,
    float* __restrict__ out,
    int H, long total)
{
    long i = (long)blockIdx.x * blockDim.x + threadIdx.x;
    if (i >= total) return;
    int row = (int)(i / H);
    float scale_x = scale_x_v[row];
    float scale_y = scale_y_v[row];
    float f   = decode_elem(x[i]);
    float xf  = f * scale_x;
    float e   = exp2f(-xf * LOG2E);
    float sig = __frcp_rn(1.0f + e);
    float yq  = fminf(rintf(sig / scale_y), 127.0f);
    float oq  = rintf(xf * (yq * scale_y) / scale_out_v[row]);
    out[i] = fminf(fmaxf(oq, -127.0f), 127.0f);
}

__global__ void tail_pad_kernel(const float* __restrict__ scale_o,
                                float* __restrict__ dst, int S, long extra) {
    long i = (long)blockIdx.x * blockDim.x + threadIdx.x;
    if (i >= extra) return;
    dst[i] = (i < S) ? scale_o[i] : 0.0f;
}

extern "C" void kernel_launch(void* const* d_in, const int* in_sizes, int n_in,
                              void* d_out, int out_size) {
    const void* x         = d_in[0];
    const float* scale_x  = (const float*)d_in[1];
    const float* scale_y  = (const float*)d_in[2];
    const float* scale_o  = (const float*)d_in[3];

    int S = in_sizes[1];            // rows (scale_x element count)
    int H = in_sizes[0] / S;        // cols
    long total = (long)S * H;
    long extra = (long)out_size - total;
    float* out = (float*)d_out;

    if (H == 4096) {
        int write_tail = (extra >= (long)S) ? 1 : 0;
        silu_lut_kernel<<<S, 256>>>(
            (const int4*)x, scale_x, scale_y, scale_o,
            (float4*)out, out + total, write_tail);
        if (extra > (long)S) {
            long pad = extra - S;
            tail_pad_kernel<<<(int)((pad + 255) / 256), 256>>>(
                scale_o + S, out + total + S, 0, pad);
        } else if (extra > 0 && !write_tail) {
            tail_pad_kernel<<<(int)((extra + 255) / 256), 256>>>(
                scale_o, out + total, (int)extra, extra);
        }
    } else {
        long blocks = (total + 255) / 256;
        silu_quant_generic_kernel<<<(unsigned)blocks, 256>>>(
            (const int*)x, scale_x, scale_y, scale_o, out, H, total);
        if (extra > 0) {
            tail_pad_kernel<<<(int)((extra + 255) / 256), 256>>>(
                scale_o, out + total, (int)(extra < S ? extra : S), extra);
        }
    }
}